// round 14
// baseline (speedup 1.0000x reference)
#include <cuda_runtime.h>
#include <cuda_bf16.h>
#include <cstdint>

// Problem constants
#define C_IN   128
#define NP     36864          // 192*192 pixels
#define HH     192
#define WW     192
#define NHEAD  8

// Scratch
__device__ float g_v[(size_t)256 * NP];      // v [ch][pixel]
__device__ float g_t[(size_t)NHEAD * NP];    // scores

// ---------------------------------------------------------------------------
__device__ __forceinline__ uint32_t f2tf32(float f)
{
    uint32_t r;
    asm("cvt.rna.tf32.f32 %0, %1;" : "=r"(r) : "f"(f));
    return r;
}

__device__ __forceinline__ void mma_tf32(float c[4],
                                         uint32_t a0, uint32_t a1, uint32_t a2, uint32_t a3,
                                         uint32_t b0, uint32_t b1)
{
    asm volatile(
        "mma.sync.aligned.m16n8k8.row.col.f32.tf32.tf32.f32 "
        "{%0,%1,%2,%3}, {%4,%5,%6,%7}, {%8,%9}, {%0,%1,%2,%3};\n"
        : "+f"(c[0]), "+f"(c[1]), "+f"(c[2]), "+f"(c[3])
        : "r"(a0), "r"(a1), "r"(a2), "r"(a3), "r"(b0), "r"(b1));
}

__device__ __forceinline__ void cpa16(uint32_t saddr, const void* g)
{
    asm volatile("cp.async.cg.shared.global [%0], [%1], 16;" :: "r"(saddr), "l"(g));
}

// ---------------------------------------------------------------------------
// Kernel 1: QKV projection GEMM (single-pass TF32) + fused q.k epilogue.
// CTA 128(o) x 128(p), 512 threads = 16 warps (4x4), warp tile 32x32.
// K=128 in 4 chunks of 32, 2-stage cp.async pipeline from the fp32 inputs.
//
// A-row mapping for bo<4 (q/k CTAs): warp_m w holds [16 q rows | 16 k rows]
// of head bo*2 + (w>>1), d-half (w&1): smem row 32w+i*16+g -> d = (w&1)*16+g.
// q.k pairing is intra-warp (acc[0] q x acc[1] k); the two d-halves combine
// across warp_m pairs via smem tpart + one sync.
// bo in {4,5}: plain v rows -> g_v.
// SMEM per stage: A [128][32] fp32 row-stride 36 w; B [32][128] stride 136 w.
// ---------------------------------------------------------------------------
#define ARSW   36
#define BRSW   136
#define ABYTES (128 * ARSW * 4)            // 18432
#define BBYTES (32 * BRSW * 4)             // 17408
#define STAGE  (ABYTES + BBYTES)           // 35840

__global__ __launch_bounds__(512, 2) void gemm_qkv(
    const float* __restrict__ x,
    const float* __restrict__ wq,
    const float* __restrict__ wk,
    const float* __restrict__ wv)
{
    extern __shared__ unsigned char dsm[];
    __shared__ float tpart[2][128];
    const uint32_t sbase = (uint32_t)__cvta_generic_to_shared(dsm);

    const int bp   = blockIdx.x;
    const int bo   = blockIdx.y;
    const int tid  = threadIdx.x;
    const int wid  = tid >> 5;
    const int lane = tid & 31;
    const int warp_m = wid >> 2;           // 0..3 (32-row block)
    const int warp_n = wid & 3;            // 0..3 (32-col block)

    // ---- loader precompute: 2 A-slots + 2 B-slots of 16 B per thread ----
    const float* asrc[2]; uint32_t adst[2];
    const float* bsrc[2]; uint32_t bdst[2];
#pragma unroll
    for (int l = 0; l < 2; l++) {
        int c = tid + l * 512;             // 0..1023
        {   // A: smem row = c>>3 (0..127), seg = c&7
            int row = c >> 3, seg = c & 7;
            const float* srow;
            if (bo < 4) {
                int w    = row >> 5;
                int head = bo * 2 + (w >> 1);
                int half = w & 1;
                int sub  = row & 31;
                srow = (sub < 16)
                     ? (wq + (size_t)(head * 32 + half * 16 + sub) * 128)
                     : (wk + (size_t)(head * 32 + half * 16 + sub - 16) * 128);
            } else {
                srow = wv + (size_t)((bo - 4) * 128 + row) * 128;
            }
            asrc[l] = srow + seg * 4;
            adst[l] = (uint32_t)(row * 144 + seg * 16);
        }
        {   // B: row = c>>5 (0..31 k), seg = c&31
            int row = c >> 5, seg = c & 31;
            bsrc[l] = x + (size_t)row * NP + bp * 128 + seg * 4;
            bdst[l] = (uint32_t)(ABYTES + row * 544 + seg * 16);
        }
    }

    float acc[2][4][4];
#pragma unroll
    for (int i = 0; i < 2; i++)
#pragma unroll
        for (int j = 0; j < 4; j++)
#pragma unroll
            for (int r = 0; r < 4; r++) acc[i][j][r] = 0.f;

    auto issue = [&](int kc, int st) {
        const uint32_t s0 = sbase + st * STAGE;
#pragma unroll
        for (int l = 0; l < 2; l++)
            cpa16(s0 + adst[l], asrc[l] + kc * 32);
#pragma unroll
        for (int l = 0; l < 2; l++)
            cpa16(s0 + bdst[l], bsrc[l] + (size_t)(kc * 32) * NP);
    };

    issue(0, 0);
    asm volatile("cp.async.commit_group;");

    const int g = lane >> 2;
    const int q = lane & 3;

    for (int kc = 0; kc < 4; kc++) {
        const int st = kc & 1;
        if (kc < 3) issue(kc + 1, st ^ 1);
        asm volatile("cp.async.commit_group;");
        if (kc < 3) asm volatile("cp.async.wait_group 1;");
        else        asm volatile("cp.async.wait_group 0;");
        __syncthreads();

        const float* fA = (const float*)(dsm + st * STAGE);
        const float* fB = (const float*)(dsm + st * STAGE + ABYTES);

#pragma unroll
        for (int ks = 0; ks < 4; ks++) {
            const int kw = ks * 8 + q;              // k word within chunk

            uint32_t a[2][4];
#pragma unroll
            for (int i = 0; i < 2; i++) {
                int base = (warp_m * 32 + i * 16 + g) * ARSW + kw;
                a[i][0] = f2tf32(fA[base]);
                a[i][1] = f2tf32(fA[base + 8 * ARSW]);
                a[i][2] = f2tf32(fA[base + 4]);
                a[i][3] = f2tf32(fA[base + 8 * ARSW + 4]);
            }
#pragma unroll
            for (int j = 0; j < 4; j++) {
                int bb = kw * BRSW + warp_n * 32 + j * 8 + g;
                uint32_t b0 = f2tf32(fB[bb]);
                uint32_t b1 = f2tf32(fB[bb + 4 * BRSW]);
#pragma unroll
                for (int i = 0; i < 2; i++)
                    mma_tf32(acc[i][j], a[i][0], a[i][1], a[i][2], a[i][3], b0, b1);
            }
        }
        __syncthreads();
    }

    if (bo < 4) {
        // ---- fused q.k epilogue: acc[0] = q rows, acc[1] = k rows (same cols).
        const int hloc = warp_m >> 1;      // local head 0..1
        const int half = warp_m & 1;       // d-half

        float s0v[4], s1v[4];
#pragma unroll
        for (int j = 0; j < 4; j++) {
            float s0 = acc[0][j][0] * acc[1][j][0] + acc[0][j][2] * acc[1][j][2];
            float s1 = acc[0][j][1] * acc[1][j][1] + acc[0][j][3] * acc[1][j][3];
#pragma unroll
            for (int m = 4; m <= 16; m <<= 1) {
                s0 += __shfl_xor_sync(0xffffffffu, s0, m);
                s1 += __shfl_xor_sync(0xffffffffu, s1, m);
            }
            s0v[j] = s0; s1v[j] = s1;
        }
        if (half == 0 && lane < 4) {
#pragma unroll
            for (int j = 0; j < 4; j++) {
                int pl = warp_n * 32 + j * 8 + 2 * lane;
                tpart[hloc][pl]     = s0v[j];
                tpart[hloc][pl + 1] = s1v[j];
            }
        }
        __syncthreads();
        if (half == 1 && lane < 4) {
            float* tb = g_t + (size_t)(bo * 2 + hloc) * NP + bp * 128;
#pragma unroll
            for (int j = 0; j < 4; j++) {
                int pl = warp_n * 32 + j * 8 + 2 * lane;
                float t0 = (tpart[hloc][pl]     + s0v[j]) * 0.0625f;
                float t1 = (tpart[hloc][pl + 1] + s1v[j]) * 0.0625f;
                *(float2*)(tb + pl) = make_float2(t0, t1);
            }
        }
    } else {
        // ---- v epilogue ----
#pragma unroll
        for (int i = 0; i < 2; i++) {
            int o = (bo - 4) * 128 + warp_m * 32 + i * 16 + g;
#pragma unroll
            for (int j = 0; j < 4; j++) {
                int p = bp * 128 + warp_n * 32 + j * 8 + 2 * q;
                *(float2*)(g_v + (size_t)o * NP + p)       = make_float2(acc[i][j][0], acc[i][j][1]);
                *(float2*)(g_v + (size_t)(o + 8) * NP + p) = make_float2(acc[i][j][2], acc[i][j][3]);
            }
        }
    }
}

// ---------------------------------------------------------------------------
// Kernel 3 (R12 version, reverted): 3x3 regional softmax + weighted V sum.
// grid (96, 16): block = rows {h0,h0+1}, head (y>>1), 16-ch half (y&1).
// 384 threads. Phase 1: weights for both rows. Phase 2: walk 4 input rows
// once; thread = (w-quad, ch-sub) handling channels {cl, cl+8}.
// OOB slots contribute score 0 (exp(0-m)); OOB v contributes 0.
// ---------------------------------------------------------------------------
__global__ __launch_bounds__(384, 3) void attn(float* __restrict__ out)
{
    __shared__ float w9s[2][9][192];

    const int h0   = blockIdx.x * 2;    // first output row
    const int head = blockIdx.y >> 1;   // 0..7
    const int chf  = blockIdx.y & 1;    // 0..1 channel half
    const int tid  = threadIdx.x;       // 0..383

    // ---- phase 1: softmax weights for rows h0, h0+1 ----
    {
        const int r = tid / 192;        // 0..1
        const int w = tid % 192;
        const int h = h0 + r;
        const float* tb = g_t + (size_t)head * NP;
        float sc[9];
#pragma unroll
        for (int s = 0; s < 9; s++) {
            int hh = h + s / 3 - 1;
            int ww = w + s % 3 - 1;
            float v = 0.f;
            if ((unsigned)hh < 192u && (unsigned)ww < 192u)
                v = tb[hh * WW + ww];
            sc[s] = v;
        }
        float m = sc[0];
#pragma unroll
        for (int s = 1; s < 9; s++) m = fmaxf(m, sc[s]);
        float sum = 0.f;
#pragma unroll
        for (int s = 0; s < 9; s++) { float e = __expf(sc[s] - m); sc[s] = e; sum += e; }
        float inv = 1.0f / sum;
#pragma unroll
        for (int s = 0; s < 9; s++) w9s[r][s][w] = sc[s] * inv;
    }
    __syncthreads();

    // ---- phase 2 ----
    const int qw = tid % 48;
    const int w0 = qw * 4;
    const int cl = tid / 48;                        // 0..7
    const int ch0 = head * 32 + chf * 16 + cl;      // channels ch0, ch0+8

    float o[2][2][4];
#pragma unroll
    for (int r = 0; r < 2; r++)
#pragma unroll
        for (int c = 0; c < 2; c++)
#pragma unroll
            for (int k = 0; k < 4; k++) o[r][c][k] = 0.f;

    const float* vb0 = g_v + (size_t)ch0 * NP + w0;
    const float* vb1 = vb0 + (size_t)8 * NP;

#pragma unroll
    for (int hi = 0; hi < 4; hi++) {
        const int hh = h0 - 1 + hi;
        if ((unsigned)hh >= 192u) continue;

        const float* row0 = vb0 + hh * WW;
        const float* row1 = vb1 + hh * WW;
        float4 c0 = *(const float4*)row0;
        float4 c1 = *(const float4*)row1;
        float l0 = (w0 > 0)   ? row0[-1] : 0.f;
        float r0 = (w0 < 188) ? row0[4]  : 0.f;
        float l1 = (w0 > 0)   ? row1[-1] : 0.f;
        float r1 = (w0 < 188) ? row1[4]  : 0.f;

#pragma unroll
        for (int r = 0; r < 2; r++) {
            const int dh = hi - r;                  // weight row for output h0+r
            if (dh < 0 || dh > 2) continue;
            float4 Wa = *(const float4*)&w9s[r][dh * 3 + 0][w0];
            float4 Wb = *(const float4*)&w9s[r][dh * 3 + 1][w0];
            float4 Wc = *(const float4*)&w9s[r][dh * 3 + 2][w0];

            o[r][0][0] += Wa.x * l0   + Wb.x * c0.x + Wc.x * c0.y;
            o[r][0][1] += Wa.y * c0.x + Wb.y * c0.y + Wc.y * c0.z;
            o[r][0][2] += Wa.z * c0.y + Wb.z * c0.z + Wc.z * c0.w;
            o[r][0][3] += Wa.w * c0.z + Wb.w * c0.w + Wc.w * r0;

            o[r][1][0] += Wa.x * l1   + Wb.x * c1.x + Wc.x * c1.y;
            o[r][1][1] += Wa.y * c1.x + Wb.y * c1.y + Wc.y * c1.z;
            o[r][1][2] += Wa.z * c1.y + Wb.z * c1.z + Wc.z * c1.w;
            o[r][1][3] += Wa.w * c1.z + Wb.w * c1.w + Wc.w * r1;
        }
    }

#pragma unroll
    for (int r = 0; r < 2; r++) {
        float* ob0 = out + (size_t)ch0 * NP + (h0 + r) * WW + w0;
        *(float4*)ob0 = make_float4(o[r][0][0], o[r][0][1], o[r][0][2], o[r][0][3]);
        *(float4*)(ob0 + (size_t)8 * NP) = make_float4(o[r][1][0], o[r][1][1], o[r][1][2], o[r][1][3]);
    }
}

// ---------------------------------------------------------------------------
extern "C" void kernel_launch(void* const* d_in, const int* in_sizes, int n_in,
                              void* d_out, int out_size)
{
    const float* x  = (const float*)d_in[0];
    const float* wq = (const float*)d_in[1];
    const float* wk = (const float*)d_in[2];
    const float* wv = (const float*)d_in[3];
    float* out = (float*)d_out;

    cudaFuncSetAttribute(gemm_qkv, cudaFuncAttributeMaxDynamicSharedMemorySize, 2 * STAGE);

    dim3 g1(NP / 128, 6);            // (288, 6)
    gemm_qkv<<<g1, 512, 2 * STAGE>>>(x, wq, wk, wv);

    dim3 g3(HH / 2, 16);             // (96, 16)
    attn<<<g3, 384>>>(out);
}

// round 17
// speedup vs baseline: 1.1402x; 1.1402x over previous
#include <cuda_runtime.h>
#include <cuda_bf16.h>
#include <cstdint>

// Problem constants
#define C_IN   128
#define NP     36864          // 192*192 pixels
#define HH     192
#define WW     192
#define NHEAD  8

// Scratch
__device__ float g_v[(size_t)256 * NP];      // v [ch][pixel]
__device__ float g_t[(size_t)NHEAD * NP];    // scores
__device__ __align__(16) float gWr[(size_t)768 * C_IN];  // tf32-rounded W, head-interleaved

// ---------------------------------------------------------------------------
__device__ __forceinline__ uint32_t f2tf32(float f)
{
    uint32_t r;
    asm("cvt.rna.tf32.f32 %0, %1;" : "=r"(r) : "f"(f));
    return r;
}

__device__ __forceinline__ void mma_tf32(float c[4],
                                         uint32_t a0, uint32_t a1, uint32_t a2, uint32_t a3,
                                         uint32_t b0, uint32_t b1)
{
    asm volatile(
        "mma.sync.aligned.m16n8k8.row.col.f32.tf32.tf32.f32 "
        "{%0,%1,%2,%3}, {%4,%5,%6,%7}, {%8,%9}, {%0,%1,%2,%3};\n"
        : "+f"(c[0]), "+f"(c[1]), "+f"(c[2]), "+f"(c[3])
        : "r"(a0), "r"(a1), "r"(a2), "r"(a3), "r"(b0), "r"(b1));
}

__device__ __forceinline__ void cpa16(uint32_t saddr, const void* g)
{
    asm volatile("cp.async.cg.shared.global [%0], [%1], 16;" :: "r"(saddr), "l"(g));
}

// ---------------------------------------------------------------------------
// Pre-pass: round W to tf32 (RNA) once; store fp32-container, head-interleaved
// layout: rows [0,512) = per head [32 q | 32 k]; rows [512,768) = wv.
// grid 96 x 256 (float4 per thread, 24576 float4s).
// ---------------------------------------------------------------------------
__global__ __launch_bounds__(256) void conv_w(
    const float* __restrict__ wq, const float* __restrict__ wk, const float* __restrict__ wv)
{
    int idx = (blockIdx.x * 256 + threadIdx.x) * 4;
    int row = idx >> 7, col = idx & 127;
    const float* src;
    if (row < 512) {
        int head = row >> 6, sub = row & 63;
        src = (sub < 32) ? (wq + (size_t)(head * 32 + sub) * 128)
                         : (wk + (size_t)(head * 32 + sub - 32) * 128);
    } else {
        src = wv + (size_t)(row - 512) * 128;
    }
    float4 v = *(const float4*)(src + col);
    uint4 r;
    r.x = f2tf32(v.x); r.y = f2tf32(v.y); r.z = f2tf32(v.z); r.w = f2tf32(v.w);
    *(uint4*)(gWr + idx) = r;
}

// ---------------------------------------------------------------------------
// Kernel 1: QKV projection GEMM (TF32 RNA) + fused q.k epilogue.
// R12 structure: CTA 128(o) x 128(p), 256 thr, 8 warps 2x4 (warp tile 64x32),
// K=128 in 4 chunks of 32, 2-stage cp.async.
// A comes PRE-ROUNDED from gWr (no in-loop cvt for A); B cvt.rna in-register.
// bo<4: q/k heads (2 per CTA) -> t only. bo in {4,5}: v -> g_v.
// ---------------------------------------------------------------------------
#define ARSW   36
#define BRSW   136
#define ABYTES (128 * ARSW * 4)            // 18432
#define BBYTES (32 * BRSW * 4)             // 17408
#define STAGE  (ABYTES + BBYTES)           // 35840

__global__ __launch_bounds__(256, 2) void gemm_qkv(const float* __restrict__ x)
{
    extern __shared__ unsigned char dsm[];
    const uint32_t sbase = (uint32_t)__cvta_generic_to_shared(dsm);

    const int bp   = blockIdx.x;
    const int bo   = blockIdx.y;
    const int tid  = threadIdx.x;
    const int wid  = tid >> 5;
    const int lane = tid & 31;
    const int warp_m = wid >> 2;
    const int warp_n = wid & 3;

    // ---- loader precompute: 4 A-chunks + 4 B-chunks of 16 B per thread ----
    const float* asrc[4]; uint32_t adst[4];
    const float* bsrc[4]; uint32_t bdst[4];
#pragma unroll
    for (int l = 0; l < 4; l++) {
        int c = tid + l * 256;             // 0..1023
        {   // A: row = c>>3 (0..127), seg = c&7
            int row = c >> 3, seg = c & 7;
            asrc[l] = gWr + (size_t)(bo * 128 + row) * 128 + seg * 4;
            adst[l] = (uint32_t)(row * 144 + seg * 16);
        }
        {   // B: row = c>>5 (0..31 k), seg = c&31
            int row = c >> 5, seg = c & 31;
            bsrc[l] = x + (size_t)row * NP + bp * 128 + seg * 4;
            bdst[l] = (uint32_t)(ABYTES + row * 544 + seg * 16);
        }
    }

    float acc[4][4][4];
#pragma unroll
    for (int i = 0; i < 4; i++)
#pragma unroll
        for (int j = 0; j < 4; j++)
#pragma unroll
            for (int r = 0; r < 4; r++) acc[i][j][r] = 0.f;

    auto issue = [&](int kc, int st) {
        const uint32_t s0 = sbase + st * STAGE;
#pragma unroll
        for (int l = 0; l < 4; l++)
            cpa16(s0 + adst[l], asrc[l] + kc * 32);
#pragma unroll
        for (int l = 0; l < 4; l++)
            cpa16(s0 + bdst[l], bsrc[l] + (size_t)(kc * 32) * NP);
    };

    issue(0, 0);
    asm volatile("cp.async.commit_group;");

    for (int kc = 0; kc < 4; kc++) {
        const int st = kc & 1;
        if (kc < 3) issue(kc + 1, st ^ 1);
        asm volatile("cp.async.commit_group;");
        if (kc < 3) asm volatile("cp.async.wait_group 1;");
        else        asm volatile("cp.async.wait_group 0;");
        __syncthreads();

        const uint32_t* uA = (const uint32_t*)(dsm + st * STAGE);
        const float*    fB = (const float*)(dsm + st * STAGE + ABYTES);

#pragma unroll
        for (int ks = 0; ks < 4; ks++) {
            const int kw = ks * 8 + (lane & 3);     // k word within chunk

            uint32_t a[4][4];
#pragma unroll
            for (int i = 0; i < 4; i++) {
                int base = (warp_m * 64 + i * 16 + (lane >> 2)) * ARSW + kw;
                a[i][0] = uA[base];
                a[i][1] = uA[base + 8 * ARSW];
                a[i][2] = uA[base + 4];
                a[i][3] = uA[base + 8 * ARSW + 4];
            }
#pragma unroll
            for (int j = 0; j < 4; j++) {
                int bb = kw * BRSW + warp_n * 32 + j * 8 + (lane >> 2);
                uint32_t b0 = f2tf32(fB[bb]);
                uint32_t b1 = f2tf32(fB[bb + 4 * BRSW]);
#pragma unroll
                for (int i = 0; i < 4; i++)
                    mma_tf32(acc[i][j], a[i][0], a[i][1], a[i][2], a[i][3], b0, b1);
            }
        }
        __syncthreads();
    }

    const int g = lane >> 2;
    const int q = lane & 3;

    if (bo < 4) {
        // ---- fused q.k epilogue: warp_m's 64 rows = [32 q | 32 k] of one head.
        const int head = bo * 2 + warp_m;
        float* tb = g_t + (size_t)head * NP;
#pragma unroll
        for (int j = 0; j < 4; j++) {
            float s0 = 0.f, s1 = 0.f;
#pragma unroll
            for (int i = 0; i < 2; i++) {
                s0 += acc[i][j][0] * acc[i + 2][j][0] + acc[i][j][2] * acc[i + 2][j][2];
                s1 += acc[i][j][1] * acc[i + 2][j][1] + acc[i][j][3] * acc[i + 2][j][3];
            }
#pragma unroll
            for (int m = 4; m <= 16; m <<= 1) {
                s0 += __shfl_xor_sync(0xffffffffu, s0, m);
                s1 += __shfl_xor_sync(0xffffffffu, s1, m);
            }
            if (g == 0) {
                int p = bp * 128 + warp_n * 32 + j * 8 + 2 * q;
                *(float2*)(tb + p) = make_float2(s0 * 0.0625f, s1 * 0.0625f);
            }
        }
    } else {
        // ---- v epilogue ----
#pragma unroll
        for (int i = 0; i < 4; i++) {
            int o = (bo - 4) * 128 + warp_m * 64 + i * 16 + g;
#pragma unroll
            for (int j = 0; j < 4; j++) {
                int p = bp * 128 + warp_n * 32 + j * 8 + 2 * q;
                *(float2*)(g_v + (size_t)o * NP + p)       = make_float2(acc[i][j][0], acc[i][j][1]);
                *(float2*)(g_v + (size_t)(o + 8) * NP + p) = make_float2(acc[i][j][2], acc[i][j][3]);
            }
        }
    }
}

// ---------------------------------------------------------------------------
// Kernel 3 (R12 version): 3x3 regional softmax + weighted V sum.
// grid (96, 16): block = rows {h0,h0+1}, head (y>>1), 16-ch half (y&1).
// 384 threads. Phase 1: weights for both rows. Phase 2: walk 4 input rows
// once; thread = (w-quad, ch-sub) handling channels {cl, cl+8}.
// OOB slots contribute score 0 (exp(0-m)); OOB v contributes 0.
// ---------------------------------------------------------------------------
__global__ __launch_bounds__(384, 3) void attn(float* __restrict__ out)
{
    __shared__ float w9s[2][9][192];

    const int h0   = blockIdx.x * 2;    // first output row
    const int head = blockIdx.y >> 1;   // 0..7
    const int chf  = blockIdx.y & 1;    // 0..1 channel half
    const int tid  = threadIdx.x;       // 0..383

    // ---- phase 1: softmax weights for rows h0, h0+1 ----
    {
        const int r = tid / 192;        // 0..1
        const int w = tid % 192;
        const int h = h0 + r;
        const float* tb = g_t + (size_t)head * NP;
        float sc[9];
#pragma unroll
        for (int s = 0; s < 9; s++) {
            int hh = h + s / 3 - 1;
            int ww = w + s % 3 - 1;
            float v = 0.f;
            if ((unsigned)hh < 192u && (unsigned)ww < 192u)
                v = tb[hh * WW + ww];
            sc[s] = v;
        }
        float m = sc[0];
#pragma unroll
        for (int s = 1; s < 9; s++) m = fmaxf(m, sc[s]);
        float sum = 0.f;
#pragma unroll
        for (int s = 0; s < 9; s++) { float e = __expf(sc[s] - m); sc[s] = e; sum += e; }
        float inv = 1.0f / sum;
#pragma unroll
        for (int s = 0; s < 9; s++) w9s[r][s][w] = sc[s] * inv;
    }
    __syncthreads();

    // ---- phase 2 ----
    const int qw = tid % 48;
    const int w0 = qw * 4;
    const int cl = tid / 48;                        // 0..7
    const int ch0 = head * 32 + chf * 16 + cl;      // channels ch0, ch0+8

    float o[2][2][4];
#pragma unroll
    for (int r = 0; r < 2; r++)
#pragma unroll
        for (int c = 0; c < 2; c++)
#pragma unroll
            for (int k = 0; k < 4; k++) o[r][c][k] = 0.f;

    const float* vb0 = g_v + (size_t)ch0 * NP + w0;
    const float* vb1 = vb0 + (size_t)8 * NP;

#pragma unroll
    for (int hi = 0; hi < 4; hi++) {
        const int hh = h0 - 1 + hi;
        if ((unsigned)hh >= 192u) continue;

        const float* row0 = vb0 + hh * WW;
        const float* row1 = vb1 + hh * WW;
        float4 c0 = *(const float4*)row0;
        float4 c1 = *(const float4*)row1;
        float l0 = (w0 > 0)   ? row0[-1] : 0.f;
        float r0 = (w0 < 188) ? row0[4]  : 0.f;
        float l1 = (w0 > 0)   ? row1[-1] : 0.f;
        float r1 = (w0 < 188) ? row1[4]  : 0.f;

#pragma unroll
        for (int r = 0; r < 2; r++) {
            const int dh = hi - r;                  // weight row for output h0+r
            if (dh < 0 || dh > 2) continue;
            float4 Wa = *(const float4*)&w9s[r][dh * 3 + 0][w0];
            float4 Wb = *(const float4*)&w9s[r][dh * 3 + 1][w0];
            float4 Wc = *(const float4*)&w9s[r][dh * 3 + 2][w0];

            o[r][0][0] += Wa.x * l0   + Wb.x * c0.x + Wc.x * c0.y;
            o[r][0][1] += Wa.y * c0.x + Wb.y * c0.y + Wc.y * c0.z;
            o[r][0][2] += Wa.z * c0.y + Wb.z * c0.z + Wc.z * c0.w;
            o[r][0][3] += Wa.w * c0.z + Wb.w * c0.w + Wc.w * r0;

            o[r][1][0] += Wa.x * l1   + Wb.x * c1.x + Wc.x * c1.y;
            o[r][1][1] += Wa.y * c1.x + Wb.y * c1.y + Wc.y * c1.z;
            o[r][1][2] += Wa.z * c1.y + Wb.z * c1.z + Wc.z * c1.w;
            o[r][1][3] += Wa.w * c1.z + Wb.w * c1.w + Wc.w * r1;
        }
    }

#pragma unroll
    for (int r = 0; r < 2; r++) {
        float* ob0 = out + (size_t)ch0 * NP + (h0 + r) * WW + w0;
        *(float4*)ob0 = make_float4(o[r][0][0], o[r][0][1], o[r][0][2], o[r][0][3]);
        *(float4*)(ob0 + (size_t)8 * NP) = make_float4(o[r][1][0], o[r][1][1], o[r][1][2], o[r][1][3]);
    }
}

// ---------------------------------------------------------------------------
extern "C" void kernel_launch(void* const* d_in, const int* in_sizes, int n_in,
                              void* d_out, int out_size)
{
    const float* x  = (const float*)d_in[0];
    const float* wq = (const float*)d_in[1];
    const float* wk = (const float*)d_in[2];
    const float* wv = (const float*)d_in[3];
    float* out = (float*)d_out;

    cudaFuncSetAttribute(gemm_qkv, cudaFuncAttributeMaxDynamicSharedMemorySize, 2 * STAGE);

    conv_w<<<96, 256>>>(wq, wk, wv);

    dim3 g1(NP / 128, 6);            // (288, 6)
    gemm_qkv<<<g1, 256, 2 * STAGE>>>(x);

    dim3 g3(HH / 2, 16);             // (96, 16)
    attn<<<g3, 384>>>(out);
}